// round 4
// baseline (speedup 1.0000x reference)
#include <cuda_runtime.h>
#include <cuda_bf16.h>
#include <cstdint>

// ---------------------------------------------------------------------------
// Swin window attention: B_=2048, N=49, H=16, D=32, C=512, nW=64, fp32.
// Split-bf16 (hi/lo) HMMA GEMMs with precomputed operands + cp.async pipeline,
// register-microtiled fused attention.
// ---------------------------------------------------------------------------
#define B_TOT   2048
#define NTOK    49
#define NPAD    56
#define NHEAD   16
#define HDIM    32
#define CDIM    512
#define NWIN    64
#define QK_SCALE 0.17677669529663687f
#define M_ROWS  (B_TOT * NTOK)          // 100352 = 784 * 128

// Scratch
__device__ float          g_qkv[(size_t)M_ROWS * 3 * CDIM];
__device__ __nv_bfloat16  g_xh [(size_t)M_ROWS * CDIM];
__device__ __nv_bfloat16  g_xl [(size_t)M_ROWS * CDIM];
__device__ __nv_bfloat16  g_aoh[(size_t)M_ROWS * CDIM];
__device__ __nv_bfloat16  g_aol[(size_t)M_ROWS * CDIM];
__device__ __nv_bfloat16  g_wqh[3 * CDIM * CDIM];
__device__ __nv_bfloat16  g_wql[3 * CDIM * CDIM];
__device__ __nv_bfloat16  g_wph[CDIM * CDIM];
__device__ __nv_bfloat16  g_wpl[CDIM * CDIM];

// ---------------------------------------------------------------------------
__device__ __forceinline__ uint32_t smem_u32(const void* p) {
    uint32_t a;
    asm("{ .reg .u64 t; cvta.to.shared.u64 t, %1; cvt.u32.u64 %0, t; }"
        : "=r"(a) : "l"(p));
    return a;
}

// fp32 pair -> (hi bf16x2, lo residual bf16x2)
__device__ __forceinline__ void cvt_pair(float x, float y, uint32_t& hp, uint32_t& lp) {
    unsigned short h0 = __bfloat16_as_ushort(__float2bfloat16_rn(x));
    unsigned short h1 = __bfloat16_as_ushort(__float2bfloat16_rn(y));
    hp = (uint32_t)h0 | ((uint32_t)h1 << 16);
    float l0 = x - __uint_as_float((uint32_t)h0 << 16);
    float l1 = y - __uint_as_float((uint32_t)h1 << 16);
    asm("cvt.rn.bf16x2.f32 %0, %1, %2;" : "=r"(lp) : "f"(l1), "f"(l0));
}

#define LDSM4(r, addr) \
    asm volatile("ldmatrix.sync.aligned.m8n8.x4.shared.b16 {%0,%1,%2,%3}, [%4];" \
        : "=r"((r)[0]), "=r"((r)[1]), "=r"((r)[2]), "=r"((r)[3]) : "r"(addr))

#define MMA16816(d, a, b0, b1) \
    asm volatile("mma.sync.aligned.m16n8k16.row.col.f32.bf16.bf16.f32 " \
        "{%0,%1,%2,%3}, {%4,%5,%6,%7}, {%8,%9}, {%0,%1,%2,%3};" \
        : "+f"((d)[0]), "+f"((d)[1]), "+f"((d)[2]), "+f"((d)[3]) \
        : "r"((a)[0]), "r"((a)[1]), "r"((a)[2]), "r"((a)[3]), "r"(b0), "r"(b1))

#define CP16(saddr, gaddr) \
    asm volatile("cp.async.cg.shared.global [%0], [%1], 16;" :: "r"(saddr), "l"(gaddr))
#define CP_COMMIT() asm volatile("cp.async.commit_group;" ::: "memory")
#define CP_WAIT1()  asm volatile("cp.async.wait_group 1;" ::: "memory")
#define CP_WAIT0()  asm volatile("cp.async.wait_group 0;" ::: "memory")

// ---------------------------------------------------------------------------
// fp32 -> split bf16 hi/lo conversion pass (vectorized)
// ---------------------------------------------------------------------------
__global__ void split_bf16_kernel(const float4* __restrict__ src,
                                  uint2* __restrict__ dh, uint2* __restrict__ dl,
                                  int n4)
{
    int i = blockIdx.x * blockDim.x + threadIdx.x;
    if (i < n4) {
        float4 v = src[i];
        uint32_t h0, l0, h1, l1;
        cvt_pair(v.x, v.y, h0, l0);
        cvt_pair(v.z, v.w, h1, l1);
        dh[i] = make_uint2(h0, h1);
        dl[i] = make_uint2(l0, l1);
    }
}

// ---------------------------------------------------------------------------
// HMMA split-bf16 GEMM: C[M,N] = A[M,K]*W[N,K]^T + bias, bf16 hi/lo operands.
// CTA 128x128, BK=32, 256 threads, 2-stage cp.async, warp tile 64x32.
// smem row: 32 bf16 payload (64B), 80B stride -> conflict-free ldmatrix.
// ---------------------------------------------------------------------------
#define ROWB      80
#define TILE_SZ   10240            // 128 rows * 80B
#define STAGE_SZ  40960            // AH AL BH BL
#define SMEM_GEMM 81920

__global__ __launch_bounds__(256, 2)
void hmma_gemm(const __nv_bfloat16* __restrict__ Ah, const __nv_bfloat16* __restrict__ Al,
               const __nv_bfloat16* __restrict__ Bh, const __nv_bfloat16* __restrict__ Bl,
               const float* __restrict__ bias, float* __restrict__ C,
               int N, int K)
{
    extern __shared__ char sm[];
    const uint32_t sb = smem_u32(sm);

    const int tid = threadIdx.x;
    const int wid = tid >> 5, lid = tid & 31;
    const int warp_m = wid & 1;
    const int warp_n = wid >> 1;
    const int m0 = blockIdx.y * 128;
    const int n0 = blockIdx.x * 128;

    // cp.async chunk mapping: 2048 16B-chunks/stage, 8 per thread
    const __nv_bfloat16* gbase[4] = {
        Ah + (size_t)m0 * K, Al + (size_t)m0 * K,
        Bh + (size_t)n0 * K, Bl + (size_t)n0 * K };

    // ldmatrix lane addresses (stage-relative)
    const uint32_t aRow  = (uint32_t)(warp_m * 64 + (lid & 15));
    const uint32_t aKoff = (uint32_t)((lid >> 4) << 4);
    const uint32_t bRow  = (uint32_t)(warp_n * 32 + ((lid >> 4) << 3) + (lid & 7));
    const uint32_t bKoff = (uint32_t)(((lid >> 3) & 1) << 4);
    const uint32_t aOff = aRow * ROWB + aKoff;
    const uint32_t bOff = bRow * ROWB + bKoff;

    float acc[4][4][4];
#pragma unroll
    for (int i = 0; i < 4; i++)
#pragma unroll
        for (int j = 0; j < 4; j++)
#pragma unroll
            for (int e = 0; e < 4; e++) acc[i][j][e] = 0.f;

    const int iters = K / 32;

    // issue stage helper (inlined twice)
#define ISSUE_STAGE(it, buf) do {                                             \
        const int kblk = (it) * 32;                                           \
        const uint32_t stb = sb + (buf) * STAGE_SZ;                           \
        _Pragma("unroll")                                                     \
        for (int s = 0; s < 8; s++) {                                         \
            const int id   = tid + s * 256;                                   \
            const int tile = id >> 9;                                         \
            const int row  = (id >> 2) & 127;                                 \
            const int c    = id & 3;                                          \
            CP16(stb + tile * TILE_SZ + row * ROWB + c * 16,                  \
                 gbase[tile] + (size_t)row * K + kblk + c * 8);               \
        }                                                                     \
    } while (0)

    ISSUE_STAGE(0, 0);
    CP_COMMIT();

    for (int i = 0; i < iters; i++) {
        const int buf = i & 1;
        if (i + 1 < iters) {
            ISSUE_STAGE(i + 1, buf ^ 1);
            CP_COMMIT();
            CP_WAIT1();
        } else {
            CP_WAIT0();
        }
        __syncthreads();

        const uint32_t st = sb + buf * STAGE_SZ;
        const uint32_t aHi = st + aOff;
        const uint32_t aLo = st + TILE_SZ + aOff;
        const uint32_t bHi = st + 2 * TILE_SZ + bOff;
        const uint32_t bLo = st + 3 * TILE_SZ + bOff;

#pragma unroll
        for (int ks = 0; ks < 2; ks++) {
            const uint32_t ko = (uint32_t)(ks * 32);
            uint32_t bh[2][4], bl[2][4];
            LDSM4(bh[0], bHi + ko);
            LDSM4(bh[1], bHi + ko + 16 * ROWB);
            LDSM4(bl[0], bLo + ko);
            LDSM4(bl[1], bLo + ko + 16 * ROWB);
#pragma unroll
            for (int mi = 0; mi < 4; mi++) {
                uint32_t ah[4], al[4];
                LDSM4(ah, aHi + ko + mi * (16 * ROWB));
                LDSM4(al, aLo + ko + mi * (16 * ROWB));
#pragma unroll
                for (int nj = 0; nj < 4; nj++) {
                    const uint32_t* bph = bh[nj >> 1] + ((nj & 1) << 1);
                    const uint32_t* bpl = bl[nj >> 1] + ((nj & 1) << 1);
                    MMA16816(acc[mi][nj], ah, bph[0], bph[1]);
                    MMA16816(acc[mi][nj], ah, bpl[0], bpl[1]);
                    MMA16816(acc[mi][nj], al, bph[0], bph[1]);
                }
            }
        }
        __syncthreads();
    }
#undef ISSUE_STAGE

    // Epilogue
    const int l4 = lid >> 2;
    const int lc = (lid & 3) * 2;
#pragma unroll
    for (int mi = 0; mi < 4; mi++) {
        const int row = m0 + warp_m * 64 + mi * 16 + l4;
#pragma unroll
        for (int nj = 0; nj < 4; nj++) {
            const int col = n0 + warp_n * 32 + nj * 8 + lc;
            const float b0 = bias[col], b1 = bias[col + 1];
            float2 v0 = make_float2(acc[mi][nj][0] + b0, acc[mi][nj][1] + b1);
            float2 v1 = make_float2(acc[mi][nj][2] + b0, acc[mi][nj][3] + b1);
            *(float2*)(C + (size_t)row * N + col)       = v0;
            *(float2*)(C + (size_t)(row + 8) * N + col) = v1;
        }
    }
}

// ---------------------------------------------------------------------------
// Fused window attention, register-microtiled. One CTA per (window, head).
// Writes output as split bf16 hi/lo (proj GEMM consumes directly).
// ---------------------------------------------------------------------------
__global__ __launch_bounds__(128)
void window_attn_kernel(const float* __restrict__ qkv,
                        const float* __restrict__ mask,
                        const float* __restrict__ rpb,
                        __nv_bfloat16* __restrict__ aoh,
                        __nv_bfloat16* __restrict__ aol)
{
    const int b = blockIdx.x >> 4;
    const int h = blockIdx.x & 15;
    const int tid = threadIdx.x;
    const int wid = tid >> 5, lid = tid & 31;

    __shared__ float qs[NPAD][36];
    __shared__ float ks[NPAD][36];
    __shared__ float vs[NPAD][36];
    __shared__ float sc[NPAD][NPAD];

    // Load q (scaled), k, v; zero pad rows 49..55
    const size_t base = (size_t)b * NTOK * (3 * CDIM) + h * HDIM;
    for (int idx = tid; idx < NTOK * HDIM; idx += 128) {
        const int n = idx >> 5, d = idx & 31;
        const size_t off = base + (size_t)n * (3 * CDIM) + d;
        qs[n][d] = qkv[off] * QK_SCALE;
        ks[n][d] = qkv[off + CDIM];
        vs[n][d] = qkv[off + 2 * CDIM];
    }
    for (int idx = tid; idx < (NPAD - NTOK) * HDIM; idx += 128) {
        const int n = NTOK + (idx >> 5), d = idx & 31;
        qs[n][d] = 0.f; ks[n][d] = 0.f; vs[n][d] = 0.f;
    }
    __syncthreads();

    // Scores: 98 tiles of 4 rows x 8 cols (56x56 padded)
    const float* mrow = mask + (size_t)(b & (NWIN - 1)) * NTOK * NTOK;
    if (tid < 98) {
        const int n0t = (tid / 7) * 4;
        const int m0t = (tid % 7) * 8;
        float a[4][8];
#pragma unroll
        for (int i = 0; i < 4; i++)
#pragma unroll
            for (int j = 0; j < 8; j++) a[i][j] = 0.f;
#pragma unroll
        for (int d4 = 0; d4 < 8; d4++) {
            float4 q4[4], k4[8];
#pragma unroll
            for (int i = 0; i < 4; i++) q4[i] = *(float4*)&qs[n0t + i][d4 * 4];
#pragma unroll
            for (int j = 0; j < 8; j++) k4[j] = *(float4*)&ks[m0t + j][d4 * 4];
#pragma unroll
            for (int i = 0; i < 4; i++)
#pragma unroll
                for (int j = 0; j < 8; j++) {
                    a[i][j] += q4[i].x * k4[j].x + q4[i].y * k4[j].y
                             + q4[i].z * k4[j].z + q4[i].w * k4[j].w;
                }
        }
#pragma unroll
        for (int i = 0; i < 4; i++) {
            const int n = n0t + i;
#pragma unroll
            for (int j = 0; j < 8; j++) {
                const int m = m0t + j;
                float v;
                if (n < NTOK && m < NTOK) {
                    const int ridx = (n / 7 - m / 7 + 6) * 13 + (n % 7 - m % 7 + 6);
                    v = a[i][j] + rpb[ridx * NHEAD + h] + mrow[n * NTOK + m];
                } else {
                    v = -3.0e38f;
                }
                sc[n][m] = v;
            }
        }
    }
    __syncthreads();

    // Warp-per-row softmax over 56 cols (pad cols are -inf -> 0)
    for (int r = wid; r < NTOK; r += 4) {
        float v0 = sc[r][lid];
        float v1 = (lid < NPAD - 32) ? sc[r][lid + 32] : -3.0e38f;
        float mx = fmaxf(v0, v1);
#pragma unroll
        for (int o = 16; o; o >>= 1) mx = fmaxf(mx, __shfl_xor_sync(~0u, mx, o));
        float e0 = __expf(v0 - mx);
        float e1 = (lid < NPAD - 32) ? __expf(v1 - mx) : 0.f;
        float s = e0 + e1;
#pragma unroll
        for (int o = 16; o; o >>= 1) s += __shfl_xor_sync(~0u, s, o);
        const float inv = 1.f / s;
        sc[r][lid] = e0 * inv;
        if (lid < NPAD - 32) sc[r][lid + 32] = e1 * inv;
    }
    __syncthreads();

    // PV: 104 tiles of 4 rows x 4 dims; m runs 0..51 (pad contributes 0)
    if (tid < 104) {
        const int n0t = (tid >> 3) * 4;        // 0..48
        const int d0t = (tid & 7) * 4;         // 0..28
        float a[4][4];
#pragma unroll
        for (int i = 0; i < 4; i++)
#pragma unroll
            for (int j = 0; j < 4; j++) a[i][j] = 0.f;
#pragma unroll
        for (int m4 = 0; m4 < 13; m4++) {
            float4 s4[4], v4[4];
#pragma unroll
            for (int i = 0; i < 4; i++) s4[i] = *(float4*)&sc[n0t + i][m4 * 4];
#pragma unroll
            for (int k = 0; k < 4; k++) v4[k] = *(float4*)&vs[m4 * 4 + k][d0t];
#pragma unroll
            for (int i = 0; i < 4; i++) {
#pragma unroll
                for (int j = 0; j < 4; j++) {
                    a[i][j] += s4[i].x * (&v4[0].x)[j] + s4[i].y * (&v4[1].x)[j]
                             + s4[i].z * (&v4[2].x)[j] + s4[i].w * (&v4[3].x)[j];
                }
            }
        }
#pragma unroll
        for (int i = 0; i < 4; i++) {
            const int n = n0t + i;
            if (n < NTOK) {
                const size_t o = (size_t)(b * NTOK + n) * CDIM + h * HDIM + d0t;
                uint32_t h0, l0, h1, l1;
                cvt_pair(a[i][0], a[i][1], h0, l0);
                cvt_pair(a[i][2], a[i][3], h1, l1);
                *(uint2*)(aoh + o) = make_uint2(h0, h1);
                *(uint2*)(aol + o) = make_uint2(l0, l1);
            }
        }
    }
}

// ---------------------------------------------------------------------------
extern "C" void kernel_launch(void* const* d_in, const int* in_sizes, int n_in,
                              void* d_out, int out_size)
{
    const float* x      = (const float*)d_in[0];
    const float* mask   = (const float*)d_in[1];
    const float* rpb    = (const float*)d_in[2];
    const float* qkv_w  = (const float*)d_in[3];
    const float* qkv_b  = (const float*)d_in[4];
    const float* proj_w = (const float*)d_in[5];
    const float* proj_b = (const float*)d_in[6];
    float* out = (float*)d_out;

    float *qkv_ptr = nullptr;
    __nv_bfloat16 *xh, *xl, *aoh, *aol, *wqh, *wql, *wph, *wpl;
    cudaGetSymbolAddress((void**)&qkv_ptr, g_qkv);
    cudaGetSymbolAddress((void**)&xh,  g_xh);
    cudaGetSymbolAddress((void**)&xl,  g_xl);
    cudaGetSymbolAddress((void**)&aoh, g_aoh);
    cudaGetSymbolAddress((void**)&aol, g_aol);
    cudaGetSymbolAddress((void**)&wqh, g_wqh);
    cudaGetSymbolAddress((void**)&wql, g_wql);
    cudaGetSymbolAddress((void**)&wph, g_wph);
    cudaGetSymbolAddress((void**)&wpl, g_wpl);

    static bool cfg = false;
    if (!cfg) {
        cudaFuncSetAttribute(hmma_gemm, cudaFuncAttributeMaxDynamicSharedMemorySize,
                             SMEM_GEMM);
        cfg = true;
    }

    // 0) split fp32 -> bf16 hi/lo (x and both weights)
    {
        int n4 = (M_ROWS * CDIM) / 4;
        split_bf16_kernel<<<(n4 + 255) / 256, 256>>>(
            (const float4*)x, (uint2*)xh, (uint2*)xl, n4);
        n4 = (3 * CDIM * CDIM) / 4;
        split_bf16_kernel<<<(n4 + 255) / 256, 256>>>(
            (const float4*)qkv_w, (uint2*)wqh, (uint2*)wql, n4);
        n4 = (CDIM * CDIM) / 4;
        split_bf16_kernel<<<(n4 + 255) / 256, 256>>>(
            (const float4*)proj_w, (uint2*)wph, (uint2*)wpl, n4);
    }

    // 1) QKV projection
    hmma_gemm<<<dim3((3 * CDIM) / 128, M_ROWS / 128), 256, SMEM_GEMM>>>(
        xh, xl, wqh, wql, qkv_b, qkv_ptr, 3 * CDIM, CDIM);

    // 2) Fused window attention (emits split-bf16 output)
    window_attn_kernel<<<B_TOT * NHEAD, 128>>>(qkv_ptr, mask, rpb, aoh, aol);

    // 3) Output projection
    hmma_gemm<<<dim3(CDIM / 128, M_ROWS / 128), 256, SMEM_GEMM>>>(
        aoh, aol, wph, wpl, proj_b, out, CDIM, CDIM);
}

// round 5
// speedup vs baseline: 1.1284x; 1.1284x over previous
#include <cuda_runtime.h>
#include <cuda_bf16.h>
#include <cstdint>

// ---------------------------------------------------------------------------
// Swin window attention: B_=2048, N=49, H=16, D=32, C=512, nW=64, fp32.
// Split-bf16 HMMA GEMMs (4-stage cp.async) + conflict-free fused attention.
// ---------------------------------------------------------------------------
#define B_TOT   2048
#define NTOK    49
#define NHEAD   16
#define HDIM    32
#define CDIM    512
#define NWIN    64
#define QK_SCALE 0.17677669529663687f
#define M_ROWS  (B_TOT * NTOK)          // 100352 = 784 * 128

__device__ float          g_qkv[(size_t)M_ROWS * 3 * CDIM];
__device__ __nv_bfloat16  g_xh [(size_t)M_ROWS * CDIM];
__device__ __nv_bfloat16  g_xl [(size_t)M_ROWS * CDIM];
__device__ __nv_bfloat16  g_aoh[(size_t)M_ROWS * CDIM];
__device__ __nv_bfloat16  g_aol[(size_t)M_ROWS * CDIM];
__device__ __nv_bfloat16  g_wqh[3 * CDIM * CDIM];
__device__ __nv_bfloat16  g_wql[3 * CDIM * CDIM];
__device__ __nv_bfloat16  g_wph[CDIM * CDIM];
__device__ __nv_bfloat16  g_wpl[CDIM * CDIM];

// ---------------------------------------------------------------------------
__device__ __forceinline__ uint32_t smem_u32(const void* p) {
    uint32_t a;
    asm("{ .reg .u64 t; cvta.to.shared.u64 t, %1; cvt.u32.u64 %0, t; }"
        : "=r"(a) : "l"(p));
    return a;
}

__device__ __forceinline__ void cvt_pair(float x, float y, uint32_t& hp, uint32_t& lp) {
    unsigned short h0 = __bfloat16_as_ushort(__float2bfloat16_rn(x));
    unsigned short h1 = __bfloat16_as_ushort(__float2bfloat16_rn(y));
    hp = (uint32_t)h0 | ((uint32_t)h1 << 16);
    float l0 = x - __uint_as_float((uint32_t)h0 << 16);
    float l1 = y - __uint_as_float((uint32_t)h1 << 16);
    asm("cvt.rn.bf16x2.f32 %0, %1, %2;" : "=r"(lp) : "f"(l1), "f"(l0));
}

#define LDSM4(r, addr) \
    asm volatile("ldmatrix.sync.aligned.m8n8.x4.shared.b16 {%0,%1,%2,%3}, [%4];" \
        : "=r"((r)[0]), "=r"((r)[1]), "=r"((r)[2]), "=r"((r)[3]) : "r"(addr))

#define MMA16816(d, a, b0, b1) \
    asm volatile("mma.sync.aligned.m16n8k16.row.col.f32.bf16.bf16.f32 " \
        "{%0,%1,%2,%3}, {%4,%5,%6,%7}, {%8,%9}, {%0,%1,%2,%3};" \
        : "+f"((d)[0]), "+f"((d)[1]), "+f"((d)[2]), "+f"((d)[3]) \
        : "r"((a)[0]), "r"((a)[1]), "r"((a)[2]), "r"((a)[3]), "r"(b0), "r"(b1))

#define CP16(saddr, gaddr) \
    asm volatile("cp.async.cg.shared.global [%0], [%1], 16;" :: "r"(saddr), "l"(gaddr))
#define CP_COMMIT() asm volatile("cp.async.commit_group;" ::: "memory")
#define CP_WAIT(n)  asm volatile("cp.async.wait_group %0;" :: "n"(n) : "memory")

// ---------------------------------------------------------------------------
__global__ void split_bf16_kernel(const float4* __restrict__ src,
                                  uint2* __restrict__ dh, uint2* __restrict__ dl,
                                  int n4)
{
    int i = blockIdx.x * blockDim.x + threadIdx.x;
    if (i < n4) {
        float4 v = src[i];
        uint32_t h0, l0, h1, l1;
        cvt_pair(v.x, v.y, h0, l0);
        cvt_pair(v.z, v.w, h1, l1);
        dh[i] = make_uint2(h0, h1);
        dl[i] = make_uint2(l0, l1);
    }
}

// ---------------------------------------------------------------------------
// HMMA split-bf16 GEMM: C[M,N] = A[M,K]*W[N,K]^T + bias, bf16 hi/lo operands.
// CTA 128x128, BK=16, 256 threads, 4-stage cp.async, warp tile 64x32.
// smem row: 16 bf16 payload (32B), 48B stride -> conflict-free ldmatrix.
// ---------------------------------------------------------------------------
#define ROWB      48
#define TILE_SZ   6144             // 128 rows * 48B
#define STAGE_SZ  24576            // AH AL BH BL
#define SMEM_GEMM 98304            // 4 stages

__global__ __launch_bounds__(256, 2)
void hmma_gemm(const __nv_bfloat16* __restrict__ Ah, const __nv_bfloat16* __restrict__ Al,
               const __nv_bfloat16* __restrict__ Bh, const __nv_bfloat16* __restrict__ Bl,
               const float* __restrict__ bias, float* __restrict__ C,
               int N, int K)
{
    extern __shared__ char sm[];
    const uint32_t sb = smem_u32(sm);

    const int tid = threadIdx.x;
    const int wid = tid >> 5, lid = tid & 31;
    const int warp_m = wid & 1;
    const int warp_n = wid >> 1;
    const int m0 = blockIdx.y * 128;
    const int n0 = blockIdx.x * 128;

    const __nv_bfloat16* gbase[4] = {
        Ah + (size_t)m0 * K, Al + (size_t)m0 * K,
        Bh + (size_t)n0 * K, Bl + (size_t)n0 * K };

    const uint32_t aRow  = (uint32_t)(warp_m * 64 + (lid & 15));
    const uint32_t aKoff = (uint32_t)((lid >> 4) << 4);
    const uint32_t bRow  = (uint32_t)(warp_n * 32 + ((lid >> 4) << 3) + (lid & 7));
    const uint32_t bKoff = (uint32_t)(((lid >> 3) & 1) << 4);
    const uint32_t aOff = aRow * ROWB + aKoff;
    const uint32_t bOff = bRow * ROWB + bKoff;

    float acc[4][4][4];
#pragma unroll
    for (int i = 0; i < 4; i++)
#pragma unroll
        for (int j = 0; j < 4; j++)
#pragma unroll
            for (int e = 0; e < 4; e++) acc[i][j][e] = 0.f;

    const int iters = K >> 4;      // BK=16

    // stage issue: 1024 16B chunks, 4/thread
#define ISSUE_STAGE(it) do {                                                  \
        const int kblk = (it) * 16;                                           \
        const uint32_t stb = sb + ((it) & 3) * STAGE_SZ;                      \
        _Pragma("unroll")                                                     \
        for (int s = 0; s < 4; s++) {                                         \
            const int id   = tid + s * 256;                                   \
            const int tile = id >> 8;                                         \
            const int row  = (id >> 1) & 127;                                 \
            const int c    = id & 1;                                          \
            CP16(stb + tile * TILE_SZ + row * ROWB + c * 16,                  \
                 gbase[tile] + (size_t)row * K + kblk + c * 8);               \
        }                                                                     \
    } while (0)

    ISSUE_STAGE(0); CP_COMMIT();
    ISSUE_STAGE(1); CP_COMMIT();
    ISSUE_STAGE(2); CP_COMMIT();

    for (int i = 0; i < iters; i++) {
        // stage i data ready?
        if (i < iters - 2)      CP_WAIT(2);
        else if (i == iters - 2) CP_WAIT(1);
        else                     CP_WAIT(0);
        __syncthreads();   // all warps done reading buf (i-1)&3 == (i+3)&3

        if (i + 3 < iters) { ISSUE_STAGE(i + 3); CP_COMMIT(); }

        const uint32_t st = sb + (i & 3) * STAGE_SZ;
        const uint32_t aHi = st + aOff;
        const uint32_t aLo = st + TILE_SZ + aOff;
        const uint32_t bHi = st + 2 * TILE_SZ + bOff;
        const uint32_t bLo = st + 3 * TILE_SZ + bOff;

        uint32_t bh[2][4], bl[2][4];
        LDSM4(bh[0], bHi);
        LDSM4(bh[1], bHi + 16 * ROWB);
        LDSM4(bl[0], bLo);
        LDSM4(bl[1], bLo + 16 * ROWB);
#pragma unroll
        for (int mi = 0; mi < 4; mi++) {
            uint32_t ah[4], al[4];
            LDSM4(ah, aHi + mi * (16 * ROWB));
            LDSM4(al, aLo + mi * (16 * ROWB));
#pragma unroll
            for (int nj = 0; nj < 4; nj++) {
                const uint32_t* bph = bh[nj >> 1] + ((nj & 1) << 1);
                const uint32_t* bpl = bl[nj >> 1] + ((nj & 1) << 1);
                MMA16816(acc[mi][nj], ah, bph[0], bph[1]);
                MMA16816(acc[mi][nj], ah, bpl[0], bpl[1]);
                MMA16816(acc[mi][nj], al, bph[0], bph[1]);
            }
        }
    }
#undef ISSUE_STAGE

    const int l4 = lid >> 2;
    const int lc = (lid & 3) * 2;
#pragma unroll
    for (int mi = 0; mi < 4; mi++) {
        const int row = m0 + warp_m * 64 + mi * 16 + l4;
#pragma unroll
        for (int nj = 0; nj < 4; nj++) {
            const int col = n0 + warp_n * 32 + nj * 8 + lc;
            const float b0 = bias[col], b1 = bias[col + 1];
            float2 v0 = make_float2(acc[mi][nj][0] + b0, acc[mi][nj][1] + b1);
            float2 v1 = make_float2(acc[mi][nj][2] + b0, acc[mi][nj][3] + b1);
            *(float2*)(C + (size_t)row * N + col)       = v0;
            *(float2*)(C + (size_t)(row + 8) * N + col) = v1;
        }
    }
}

// ---------------------------------------------------------------------------
// Fused window attention, conflict-free mappings, 128 threads, all active.
//   phase1: thread tile 7(n) x 4(m); ntile=tid&7, mtile=tid>>3
//           -> k float4 loads broadcast; q float4 quad-starts 28g (distinct)
//   sc stride 68 floats -> 7-row-apart store/load quads 28g (distinct)
//   phase2: dpair=tid&15, nrow=tid>>4 -> sc reads broadcast, v reads cf
// ---------------------------------------------------------------------------
#define SCPAD 68

__global__ __launch_bounds__(128)
void window_attn_kernel(const float* __restrict__ qkv,
                        const float* __restrict__ mask,
                        const float* __restrict__ rpb,
                        __nv_bfloat16* __restrict__ aoh,
                        __nv_bfloat16* __restrict__ aol)
{
    const int b = blockIdx.x >> 4;
    const int h = blockIdx.x & 15;
    const int tid = threadIdx.x;
    const int wid = tid >> 5, lid = tid & 31;

    __shared__ float qs[56][36];
    __shared__ float ks[64][36];
    __shared__ float vs[64][36];
    __shared__ float sc[56][SCPAD];

    // Load q (scaled), k, v; zero-pad q rows 49..55, k/v rows 49..63
    const size_t base = (size_t)b * NTOK * (3 * CDIM) + h * HDIM;
    for (int idx = tid; idx < NTOK * HDIM; idx += 128) {
        const int n = idx >> 5, d = idx & 31;
        const size_t off = base + (size_t)n * (3 * CDIM) + d;
        qs[n][d] = qkv[off] * QK_SCALE;
        ks[n][d] = qkv[off + CDIM];
        vs[n][d] = qkv[off + 2 * CDIM];
    }
    for (int idx = tid; idx < 15 * HDIM; idx += 128) {
        const int n = NTOK + (idx >> 5), d = idx & 31;
        if (n < 56) qs[n][d] = 0.f;
        ks[n][d] = 0.f;
        vs[n][d] = 0.f;
    }
    __syncthreads();

    // ---- phase1: scores (56x64 padded) ----
    const float* mrow = mask + (size_t)(b & (NWIN - 1)) * NTOK * NTOK;
    {
        const int nt = tid & 7;          // rows nt*7 .. nt*7+6
        const int mt = tid >> 3;         // cols mt*4 .. mt*4+3
        float a[7][4];
#pragma unroll
        for (int i = 0; i < 7; i++)
#pragma unroll
            for (int j = 0; j < 4; j++) a[i][j] = 0.f;

#pragma unroll
        for (int d4 = 0; d4 < 8; d4++) {
            float4 k4[4];
#pragma unroll
            for (int j = 0; j < 4; j++) k4[j] = *(float4*)&ks[mt * 4 + j][d4 * 4];
#pragma unroll
            for (int i = 0; i < 7; i++) {
                float4 q4 = *(float4*)&qs[nt * 7 + i][d4 * 4];
#pragma unroll
                for (int j = 0; j < 4; j++)
                    a[i][j] += q4.x * k4[j].x + q4.y * k4[j].y
                             + q4.z * k4[j].z + q4.w * k4[j].w;
            }
        }
#pragma unroll
        for (int i = 0; i < 7; i++) {
            const int n = nt * 7 + i;
#pragma unroll
            for (int j = 0; j < 4; j++) {
                const int m = mt * 4 + j;
                float v;
                if (n < NTOK && m < NTOK) {
                    const int ridx = (n / 7 - m / 7 + 6) * 13 + (n % 7 - m % 7 + 6);
                    v = a[i][j] + rpb[ridx * NHEAD + h] + mrow[n * NTOK + m];
                } else {
                    v = (n < NTOK) ? -3.0e38f : 0.f;   // pad cols -> -inf; pad rows -> 0
                }
                sc[n][m] = v;
            }
        }
    }
    __syncthreads();

    // ---- softmax: warp per row over 64 cols ----
    for (int r = wid; r < NTOK; r += 4) {
        float v0 = sc[r][lid];
        float v1 = sc[r][lid + 32];
        float mx = fmaxf(v0, v1);
#pragma unroll
        for (int o = 16; o; o >>= 1) mx = fmaxf(mx, __shfl_xor_sync(~0u, mx, o));
        float e0 = __expf(v0 - mx);
        float e1 = __expf(v1 - mx);
        float s = e0 + e1;
#pragma unroll
        for (int o = 16; o; o >>= 1) s += __shfl_xor_sync(~0u, s, o);
        const float inv = 1.f / s;
        sc[r][lid] = e0 * inv;
        sc[r][lid + 32] = e1 * inv;
    }
    __syncthreads();

    // ---- phase2: out = P @ V ----
    {
        const int dp = tid & 15;         // d cols 2dp, 2dp+1
        const int nb = tid >> 4;         // rows nb, nb+8, ..., nb+48
        float ac[7][2];
#pragma unroll
        for (int i = 0; i < 7; i++) { ac[i][0] = 0.f; ac[i][1] = 0.f; }

#pragma unroll
        for (int m4 = 0; m4 < 16; m4++) {
            float2 v2[4];
#pragma unroll
            for (int k = 0; k < 4; k++) v2[k] = *(float2*)&vs[m4 * 4 + k][dp * 2];
#pragma unroll
            for (int i = 0; i < 7; i++) {
                float4 s4 = *(float4*)&sc[nb + 8 * i][m4 * 4];
                ac[i][0] += s4.x * v2[0].x + s4.y * v2[1].x
                          + s4.z * v2[2].x + s4.w * v2[3].x;
                ac[i][1] += s4.x * v2[0].y + s4.y * v2[1].y
                          + s4.z * v2[2].y + s4.w * v2[3].y;
            }
        }
#pragma unroll
        for (int i = 0; i < 7; i++) {
            const int n = nb + 8 * i;
            if (n < NTOK) {
                const size_t o = (size_t)(b * NTOK + n) * CDIM + h * HDIM + dp * 2;
                uint32_t hp, lp;
                cvt_pair(ac[i][0], ac[i][1], hp, lp);
                *(uint32_t*)(aoh + o) = hp;
                *(uint32_t*)(aol + o) = lp;
            }
        }
    }
}

// ---------------------------------------------------------------------------
extern "C" void kernel_launch(void* const* d_in, const int* in_sizes, int n_in,
                              void* d_out, int out_size)
{
    const float* x      = (const float*)d_in[0];
    const float* mask   = (const float*)d_in[1];
    const float* rpb    = (const float*)d_in[2];
    const float* qkv_w  = (const float*)d_in[3];
    const float* qkv_b  = (const float*)d_in[4];
    const float* proj_w = (const float*)d_in[5];
    const float* proj_b = (const float*)d_in[6];
    float* out = (float*)d_out;

    float *qkv_ptr = nullptr;
    __nv_bfloat16 *xh, *xl, *aoh, *aol, *wqh, *wql, *wph, *wpl;
    cudaGetSymbolAddress((void**)&qkv_ptr, g_qkv);
    cudaGetSymbolAddress((void**)&xh,  g_xh);
    cudaGetSymbolAddress((void**)&xl,  g_xl);
    cudaGetSymbolAddress((void**)&aoh, g_aoh);
    cudaGetSymbolAddress((void**)&aol, g_aol);
    cudaGetSymbolAddress((void**)&wqh, g_wqh);
    cudaGetSymbolAddress((void**)&wql, g_wql);
    cudaGetSymbolAddress((void**)&wph, g_wph);
    cudaGetSymbolAddress((void**)&wpl, g_wpl);

    static bool cfg = false;
    if (!cfg) {
        cudaFuncSetAttribute(hmma_gemm, cudaFuncAttributeMaxDynamicSharedMemorySize,
                             SMEM_GEMM);
        cfg = true;
    }

    // 0) split fp32 -> bf16 hi/lo (x and both weights)
    {
        int n4 = (M_ROWS * CDIM) / 4;
        split_bf16_kernel<<<(n4 + 255) / 256, 256>>>(
            (const float4*)x, (uint2*)xh, (uint2*)xl, n4);
        n4 = (3 * CDIM * CDIM) / 4;
        split_bf16_kernel<<<(n4 + 255) / 256, 256>>>(
            (const float4*)qkv_w, (uint2*)wqh, (uint2*)wql, n4);
        n4 = (CDIM * CDIM) / 4;
        split_bf16_kernel<<<(n4 + 255) / 256, 256>>>(
            (const float4*)proj_w, (uint2*)wph, (uint2*)wpl, n4);
    }

    // 1) QKV projection
    hmma_gemm<<<dim3((3 * CDIM) / 128, M_ROWS / 128), 256, SMEM_GEMM>>>(
        xh, xl, wqh, wql, qkv_b, qkv_ptr, 3 * CDIM, CDIM);

    // 2) Fused window attention (emits split-bf16 output)
    window_attn_kernel<<<B_TOT * NHEAD, 128>>>(qkv_ptr, mask, rpb, aoh, aol);

    // 3) Output projection
    hmma_gemm<<<dim3(CDIM / 128, M_ROWS / 128), 256, SMEM_GEMM>>>(
        aoh, aol, wph, wpl, proj_b, out, CDIM, CDIM);
}

// round 6
// speedup vs baseline: 1.2655x; 1.1214x over previous
#include <cuda_runtime.h>
#include <cuda_bf16.h>
#include <cstdint>

// ---------------------------------------------------------------------------
// Swin window attention: B_=2048, N=49, H=16, D=32, C=512, nW=64, fp32.
// Split-bf16 HMMA GEMMs (BK=32, 2-stage cp.async) + conflict-free attention.
// ---------------------------------------------------------------------------
#define B_TOT   2048
#define NTOK    49
#define NHEAD   16
#define HDIM    32
#define CDIM    512
#define NWIN    64
#define QK_SCALE 0.17677669529663687f
#define M_ROWS  (B_TOT * NTOK)          // 100352 = 784 * 128

__device__ float          g_qkv[(size_t)M_ROWS * 3 * CDIM];
__device__ __nv_bfloat16  g_xh [(size_t)M_ROWS * CDIM];
__device__ __nv_bfloat16  g_xl [(size_t)M_ROWS * CDIM];
__device__ __nv_bfloat16  g_aoh[(size_t)M_ROWS * CDIM];
__device__ __nv_bfloat16  g_aol[(size_t)M_ROWS * CDIM];
__device__ __nv_bfloat16  g_wqh[3 * CDIM * CDIM];
__device__ __nv_bfloat16  g_wql[3 * CDIM * CDIM];
__device__ __nv_bfloat16  g_wph[CDIM * CDIM];
__device__ __nv_bfloat16  g_wpl[CDIM * CDIM];

// ---------------------------------------------------------------------------
__device__ __forceinline__ uint32_t smem_u32(const void* p) {
    uint32_t a;
    asm("{ .reg .u64 t; cvta.to.shared.u64 t, %1; cvt.u32.u64 %0, t; }"
        : "=r"(a) : "l"(p));
    return a;
}

__device__ __forceinline__ void cvt_pair(float x, float y, uint32_t& hp, uint32_t& lp) {
    unsigned short h0 = __bfloat16_as_ushort(__float2bfloat16_rn(x));
    unsigned short h1 = __bfloat16_as_ushort(__float2bfloat16_rn(y));
    hp = (uint32_t)h0 | ((uint32_t)h1 << 16);
    float l0 = x - __uint_as_float((uint32_t)h0 << 16);
    float l1 = y - __uint_as_float((uint32_t)h1 << 16);
    asm("cvt.rn.bf16x2.f32 %0, %1, %2;" : "=r"(lp) : "f"(l1), "f"(l0));
}

#define LDSM4(r, addr) \
    asm volatile("ldmatrix.sync.aligned.m8n8.x4.shared.b16 {%0,%1,%2,%3}, [%4];" \
        : "=r"((r)[0]), "=r"((r)[1]), "=r"((r)[2]), "=r"((r)[3]) : "r"(addr))

#define MMA16816(d, a, b0, b1) \
    asm volatile("mma.sync.aligned.m16n8k16.row.col.f32.bf16.bf16.f32 " \
        "{%0,%1,%2,%3}, {%4,%5,%6,%7}, {%8,%9}, {%0,%1,%2,%3};" \
        : "+f"((d)[0]), "+f"((d)[1]), "+f"((d)[2]), "+f"((d)[3]) \
        : "r"((a)[0]), "r"((a)[1]), "r"((a)[2]), "r"((a)[3]), "r"(b0), "r"(b1))

#define CP16(saddr, gaddr) \
    asm volatile("cp.async.cg.shared.global [%0], [%1], 16;" :: "r"(saddr), "l"(gaddr))
#define CP_COMMIT() asm volatile("cp.async.commit_group;" ::: "memory")
#define CP_WAIT1()  asm volatile("cp.async.wait_group 1;" ::: "memory")
#define CP_WAIT0()  asm volatile("cp.async.wait_group 0;" ::: "memory")

// ---------------------------------------------------------------------------
__global__ void split_bf16_kernel(const float4* __restrict__ src,
                                  uint2* __restrict__ dh, uint2* __restrict__ dl,
                                  int n4)
{
    int i = blockIdx.x * blockDim.x + threadIdx.x;
    if (i < n4) {
        float4 v = src[i];
        uint32_t h0, l0, h1, l1;
        cvt_pair(v.x, v.y, h0, l0);
        cvt_pair(v.z, v.w, h1, l1);
        dh[i] = make_uint2(h0, h1);
        dl[i] = make_uint2(l0, l1);
    }
}

// ---------------------------------------------------------------------------
// HMMA split-bf16 GEMM: C[M,N] = A[M,K]*W[N,K]^T + bias, bf16 hi/lo operands.
// CTA 128x128, BK=32, 256 threads, 2-stage cp.async, warp tile 64x32.
// smem row: 32 bf16 payload (64B), 80B stride -> conflict-free ldmatrix.
// ---------------------------------------------------------------------------
#define ROWB      80
#define TILE_SZ   10240            // 128 rows * 80B
#define STAGE_SZ  40960            // AH AL BH BL
#define SMEM_GEMM 81920

__global__ __launch_bounds__(256, 2)
void hmma_gemm(const __nv_bfloat16* __restrict__ Ah, const __nv_bfloat16* __restrict__ Al,
               const __nv_bfloat16* __restrict__ Bh, const __nv_bfloat16* __restrict__ Bl,
               const float* __restrict__ bias, float* __restrict__ C,
               int N, int K)
{
    extern __shared__ char sm[];
    const uint32_t sb = smem_u32(sm);

    const int tid = threadIdx.x;
    const int wid = tid >> 5, lid = tid & 31;
    const int warp_m = wid & 1;
    const int warp_n = wid >> 1;
    const int m0 = blockIdx.y * 128;
    const int n0 = blockIdx.x * 128;

    const __nv_bfloat16* gbase[4] = {
        Ah + (size_t)m0 * K, Al + (size_t)m0 * K,
        Bh + (size_t)n0 * K, Bl + (size_t)n0 * K };

    const uint32_t aRow  = (uint32_t)(warp_m * 64 + (lid & 15));
    const uint32_t aKoff = (uint32_t)((lid >> 4) << 4);
    const uint32_t bRow  = (uint32_t)(warp_n * 32 + ((lid >> 4) << 3) + (lid & 7));
    const uint32_t bKoff = (uint32_t)(((lid >> 3) & 1) << 4);
    const uint32_t aOff = aRow * ROWB + aKoff;
    const uint32_t bOff = bRow * ROWB + bKoff;

    float acc[4][4][4];
#pragma unroll
    for (int i = 0; i < 4; i++)
#pragma unroll
        for (int j = 0; j < 4; j++)
#pragma unroll
            for (int e = 0; e < 4; e++) acc[i][j][e] = 0.f;

    const int iters = K >> 5;      // BK=32

    // stage issue: 2048 16B chunks, 8 per thread
#define ISSUE_STAGE(it, buf) do {                                             \
        const int kblk = (it) * 32;                                           \
        const uint32_t stb = sb + (buf) * STAGE_SZ;                           \
        _Pragma("unroll")                                                     \
        for (int s = 0; s < 8; s++) {                                         \
            const int id   = tid + s * 256;                                   \
            const int tile = id >> 9;                                         \
            const int row  = (id >> 2) & 127;                                 \
            const int c    = id & 3;                                          \
            CP16(stb + tile * TILE_SZ + row * ROWB + c * 16,                  \
                 gbase[tile] + (size_t)row * K + kblk + c * 8);               \
        }                                                                     \
    } while (0)

    ISSUE_STAGE(0, 0);
    CP_COMMIT();

    for (int i = 0; i < iters; i++) {
        const int buf = i & 1;
        if (i + 1 < iters) {
            ISSUE_STAGE(i + 1, buf ^ 1);
            CP_COMMIT();
            CP_WAIT1();
        } else {
            CP_WAIT0();
        }
        __syncthreads();

        const uint32_t st = sb + buf * STAGE_SZ;
        const uint32_t aHi = st + aOff;
        const uint32_t aLo = st + TILE_SZ + aOff;
        const uint32_t bHi = st + 2 * TILE_SZ + bOff;
        const uint32_t bLo = st + 3 * TILE_SZ + bOff;

#pragma unroll
        for (int ks = 0; ks < 2; ks++) {
            const uint32_t ko = (uint32_t)(ks * 32);
            uint32_t bh[2][4], bl[2][4];
            LDSM4(bh[0], bHi + ko);
            LDSM4(bh[1], bHi + ko + 16 * ROWB);
            LDSM4(bl[0], bLo + ko);
            LDSM4(bl[1], bLo + ko + 16 * ROWB);
#pragma unroll
            for (int mi = 0; mi < 4; mi++) {
                uint32_t ah[4], al[4];
                LDSM4(ah, aHi + ko + mi * (16 * ROWB));
                LDSM4(al, aLo + ko + mi * (16 * ROWB));
#pragma unroll
                for (int nj = 0; nj < 4; nj++) {
                    const uint32_t* bph = bh[nj >> 1] + ((nj & 1) << 1);
                    const uint32_t* bpl = bl[nj >> 1] + ((nj & 1) << 1);
                    MMA16816(acc[mi][nj], ah, bph[0], bph[1]);
                    MMA16816(acc[mi][nj], ah, bpl[0], bpl[1]);
                    MMA16816(acc[mi][nj], al, bph[0], bph[1]);
                }
            }
        }
        __syncthreads();
    }
#undef ISSUE_STAGE

    const int l4 = lid >> 2;
    const int lc = (lid & 3) * 2;
#pragma unroll
    for (int mi = 0; mi < 4; mi++) {
        const int row = m0 + warp_m * 64 + mi * 16 + l4;
#pragma unroll
        for (int nj = 0; nj < 4; nj++) {
            const int col = n0 + warp_n * 32 + nj * 8 + lc;
            const float b0 = bias[col], b1 = bias[col + 1];
            float2 v0 = make_float2(acc[mi][nj][0] + b0, acc[mi][nj][1] + b1);
            float2 v1 = make_float2(acc[mi][nj][2] + b0, acc[mi][nj][3] + b1);
            *(float2*)(C + (size_t)row * N + col)       = v0;
            *(float2*)(C + (size_t)(row + 8) * N + col) = v1;
        }
    }
}

// ---------------------------------------------------------------------------
// Fused window attention, conflict-free mappings, 128 threads, all active.
// ---------------------------------------------------------------------------
#define SCPAD 68

__global__ __launch_bounds__(128)
void window_attn_kernel(const float* __restrict__ qkv,
                        const float* __restrict__ mask,
                        const float* __restrict__ rpb,
                        __nv_bfloat16* __restrict__ aoh,
                        __nv_bfloat16* __restrict__ aol)
{
    const int b = blockIdx.x >> 4;
    const int h = blockIdx.x & 15;
    const int tid = threadIdx.x;
    const int wid = tid >> 5, lid = tid & 31;

    __shared__ float qs[56][36];
    __shared__ float ks[64][36];
    __shared__ float vs[64][36];
    __shared__ float sc[56][SCPAD];

    const size_t base = (size_t)b * NTOK * (3 * CDIM) + h * HDIM;
    for (int idx = tid; idx < NTOK * HDIM; idx += 128) {
        const int n = idx >> 5, d = idx & 31;
        const size_t off = base + (size_t)n * (3 * CDIM) + d;
        qs[n][d] = qkv[off] * QK_SCALE;
        ks[n][d] = qkv[off + CDIM];
        vs[n][d] = qkv[off + 2 * CDIM];
    }
    for (int idx = tid; idx < 15 * HDIM; idx += 128) {
        const int n = NTOK + (idx >> 5), d = idx & 31;
        if (n < 56) qs[n][d] = 0.f;
        ks[n][d] = 0.f;
        vs[n][d] = 0.f;
    }
    __syncthreads();

    // ---- phase1: scores (56x64 padded); k loads broadcast, q conflict-free
    const float* mrow = mask + (size_t)(b & (NWIN - 1)) * NTOK * NTOK;
    {
        const int nt = tid & 7;
        const int mt = tid >> 3;
        float a[7][4];
#pragma unroll
        for (int i = 0; i < 7; i++)
#pragma unroll
            for (int j = 0; j < 4; j++) a[i][j] = 0.f;

#pragma unroll
        for (int d4 = 0; d4 < 8; d4++) {
            float4 k4[4];
#pragma unroll
            for (int j = 0; j < 4; j++) k4[j] = *(float4*)&ks[mt * 4 + j][d4 * 4];
#pragma unroll
            for (int i = 0; i < 7; i++) {
                float4 q4 = *(float4*)&qs[nt * 7 + i][d4 * 4];
#pragma unroll
                for (int j = 0; j < 4; j++)
                    a[i][j] += q4.x * k4[j].x + q4.y * k4[j].y
                             + q4.z * k4[j].z + q4.w * k4[j].w;
            }
        }
#pragma unroll
        for (int i = 0; i < 7; i++) {
            const int n = nt * 7 + i;
#pragma unroll
            for (int j = 0; j < 4; j++) {
                const int m = mt * 4 + j;
                float v;
                if (n < NTOK && m < NTOK) {
                    const int ridx = (n / 7 - m / 7 + 6) * 13 + (n % 7 - m % 7 + 6);
                    v = a[i][j] + rpb[ridx * NHEAD + h] + mrow[n * NTOK + m];
                } else {
                    v = (n < NTOK) ? -3.0e38f : 0.f;
                }
                sc[n][m] = v;
            }
        }
    }
    __syncthreads();

    // ---- softmax: warp per row over 64 cols ----
    for (int r = wid; r < NTOK; r += 4) {
        float v0 = sc[r][lid];
        float v1 = sc[r][lid + 32];
        float mx = fmaxf(v0, v1);
#pragma unroll
        for (int o = 16; o; o >>= 1) mx = fmaxf(mx, __shfl_xor_sync(~0u, mx, o));
        float e0 = __expf(v0 - mx);
        float e1 = __expf(v1 - mx);
        float s = e0 + e1;
#pragma unroll
        for (int o = 16; o; o >>= 1) s += __shfl_xor_sync(~0u, s, o);
        const float inv = 1.f / s;
        sc[r][lid] = e0 * inv;
        sc[r][lid + 32] = e1 * inv;
    }
    __syncthreads();

    // ---- phase2: out = P @ V; sc reads broadcast, v reads conflict-free
    {
        const int dp = tid & 15;
        const int nb = tid >> 4;
        float ac[7][2];
#pragma unroll
        for (int i = 0; i < 7; i++) { ac[i][0] = 0.f; ac[i][1] = 0.f; }

#pragma unroll
        for (int m4 = 0; m4 < 16; m4++) {
            float2 v2[4];
#pragma unroll
            for (int k = 0; k < 4; k++) v2[k] = *(float2*)&vs[m4 * 4 + k][dp * 2];
#pragma unroll
            for (int i = 0; i < 7; i++) {
                float4 s4 = *(float4*)&sc[nb + 8 * i][m4 * 4];
                ac[i][0] += s4.x * v2[0].x + s4.y * v2[1].x
                          + s4.z * v2[2].x + s4.w * v2[3].x;
                ac[i][1] += s4.x * v2[0].y + s4.y * v2[1].y
                          + s4.z * v2[2].y + s4.w * v2[3].y;
            }
        }
#pragma unroll
        for (int i = 0; i < 7; i++) {
            const int n = nb + 8 * i;
            if (n < NTOK) {
                const size_t o = (size_t)(b * NTOK + n) * CDIM + h * HDIM + dp * 2;
                uint32_t hp, lp;
                cvt_pair(ac[i][0], ac[i][1], hp, lp);
                *(uint32_t*)(aoh + o) = hp;
                *(uint32_t*)(aol + o) = lp;
            }
        }
    }
}

// ---------------------------------------------------------------------------
extern "C" void kernel_launch(void* const* d_in, const int* in_sizes, int n_in,
                              void* d_out, int out_size)
{
    const float* x      = (const float*)d_in[0];
    const float* mask   = (const float*)d_in[1];
    const float* rpb    = (const float*)d_in[2];
    const float* qkv_w  = (const float*)d_in[3];
    const float* qkv_b  = (const float*)d_in[4];
    const float* proj_w = (const float*)d_in[5];
    const float* proj_b = (const float*)d_in[6];
    float* out = (float*)d_out;

    float *qkv_ptr = nullptr;
    __nv_bfloat16 *xh, *xl, *aoh, *aol, *wqh, *wql, *wph, *wpl;
    cudaGetSymbolAddress((void**)&qkv_ptr, g_qkv);
    cudaGetSymbolAddress((void**)&xh,  g_xh);
    cudaGetSymbolAddress((void**)&xl,  g_xl);
    cudaGetSymbolAddress((void**)&aoh, g_aoh);
    cudaGetSymbolAddress((void**)&aol, g_aol);
    cudaGetSymbolAddress((void**)&wqh, g_wqh);
    cudaGetSymbolAddress((void**)&wql, g_wql);
    cudaGetSymbolAddress((void**)&wph, g_wph);
    cudaGetSymbolAddress((void**)&wpl, g_wpl);

    static bool cfg = false;
    if (!cfg) {
        cudaFuncSetAttribute(hmma_gemm, cudaFuncAttributeMaxDynamicSharedMemorySize,
                             SMEM_GEMM);
        cfg = true;
    }

    // 0) split fp32 -> bf16 hi/lo (x and both weights)
    {
        int n4 = (M_ROWS * CDIM) / 4;
        split_bf16_kernel<<<(n4 + 255) / 256, 256>>>(
            (const float4*)x, (uint2*)xh, (uint2*)xl, n4);
        n4 = (3 * CDIM * CDIM) / 4;
        split_bf16_kernel<<<(n4 + 255) / 256, 256>>>(
            (const float4*)qkv_w, (uint2*)wqh, (uint2*)wql, n4);
        n4 = (CDIM * CDIM) / 4;
        split_bf16_kernel<<<(n4 + 255) / 256, 256>>>(
            (const float4*)proj_w, (uint2*)wph, (uint2*)wpl, n4);
    }

    // 1) QKV projection
    hmma_gemm<<<dim3((3 * CDIM) / 128, M_ROWS / 128), 256, SMEM_GEMM>>>(
        xh, xl, wqh, wql, qkv_b, qkv_ptr, 3 * CDIM, CDIM);

    // 2) Fused window attention (emits split-bf16 output)
    window_attn_kernel<<<B_TOT * NHEAD, 128>>>(qkv_ptr, mask, rpb, aoh, aol);

    // 3) Output projection
    hmma_gemm<<<dim3(CDIM / 128, M_ROWS / 128), 256, SMEM_GEMM>>>(
        aoh, aol, wph, wpl, proj_b, out, CDIM, CDIM);
}